// round 3
// baseline (speedup 1.0000x reference)
#include <cuda_runtime.h>
#include <cstdint>

#define BROWS 131072
#define NEXp 40
#define HID 64
#define NCOLS 2560           // 40*64

// ---------- device scratch (no allocations allowed) ----------
__device__ float g_zt[HID * BROWS];   // z transposed: [d][b]
__device__ float g_wt[HID * NCOLS];   // weights transposed: [d][n], n = k*64+o
__device__ int   g_idx[BROWS];

// ---------- f32x2 packed helpers (sm_103a FFMA2 path) ----------
__device__ __forceinline__ unsigned long long pack2(float lo, float hi) {
    unsigned long long r;
    asm("mov.b64 %0, {%1, %2};" : "=l"(r) : "r"(__float_as_uint(lo)), "r"(__float_as_uint(hi)));
    return r;
}
__device__ __forceinline__ void fma2(unsigned long long& d, unsigned long long a, unsigned long long b) {
    asm("fma.rn.f32x2 %0, %1, %2, %0;" : "+l"(d) : "l"(a), "l"(b));
}
__device__ __forceinline__ void unpack2(unsigned long long v, float& lo, float& hi) {
    unsigned ulo, uhi;
    asm("mov.b64 {%0, %1}, %2;" : "=r"(ulo), "=r"(uhi) : "l"(v));
    lo = __uint_as_float(ulo); hi = __uint_as_float(uhi);
}

// ---------- JAX threefry2x32, key = (0, 1) ----------
__device__ __forceinline__ void threefry2x32_01(unsigned c0, unsigned c1,
                                                unsigned& o0, unsigned& o1) {
    const unsigned k0 = 0u, k1 = 1u, k2 = 0x1BD11BDBu; // 0 ^ 1 ^ 0x1BD11BDA
    unsigned x0 = c0 + k0;
    unsigned x1 = c1 + k1;
#define TF_R(r) { x0 += x1; x1 = (x1 << (r)) | (x1 >> (32 - (r))); x1 ^= x0; }
    TF_R(13) TF_R(15) TF_R(26) TF_R(6)   x0 += k1; x1 += k2 + 1u;
    TF_R(17) TF_R(29) TF_R(16) TF_R(24)  x0 += k2; x1 += k0 + 2u;
    TF_R(13) TF_R(15) TF_R(26) TF_R(6)   x0 += k0; x1 += k1 + 3u;
    TF_R(17) TF_R(29) TF_R(16) TF_R(24)  x0 += k1; x1 += k2 + 4u;
    TF_R(13) TF_R(15) TF_R(26) TF_R(6)   x0 += k2; x1 += k0 + 5u;
#undef TF_R
    o0 = x0; o1 = x1;
}

// ---------- kernel 0: transpose expert weights into [d][n] ----------
__global__ void k_transpose(const float* __restrict__ triz_w) {
    int t = blockIdx.x * blockDim.x + threadIdx.x;  // 163840 total
    if (t < NCOLS * HID) {
        int n = t >> 6;
        int d = t & 63;
        g_wt[d * NCOLS + n] = triz_w[t];
    }
}

// ---------- kernel 1: encoder + router softmax + threefry categorical ----------
__global__ __launch_bounds__(256) void k_encode(
    const float* __restrict__ x,
    const float* __restrict__ enc_w, const float* __restrict__ enc_b,
    const float* __restrict__ pol_w, const float* __restrict__ pol_b,
    float* __restrict__ probs_out)
{
    int b = blockIdx.x * 256 + threadIdx.x;

    float xv[5];
#pragma unroll
    for (int j = 0; j < 5; j++) xv[j] = x[b * 5 + j];

    float z[HID];
#pragma unroll
    for (int i = 0; i < HID; i++) {
        float s = enc_b[i];
#pragma unroll
        for (int j = 0; j < 5; j++) s = fmaf(xv[j], enc_w[i * 5 + j], s);
        z[i] = tanhf(s);
    }

    // write z transposed (coalesced: lanes are consecutive b)
#pragma unroll
    for (int d = 0; d < HID; d++) g_zt[d * BROWS + b] = z[d];

    // router scores
    float sc[NEXp];
    float mx = -3.4e38f;
#pragma unroll
    for (int k = 0; k < NEXp; k++) {
        float s = pol_b[k];
        const float4* w = (const float4*)(pol_w + k * HID);
#pragma unroll
        for (int q = 0; q < 16; q++) {
            float4 wv = w[q];
            s = fmaf(z[4 * q + 0], wv.x, s);
            s = fmaf(z[4 * q + 1], wv.y, s);
            s = fmaf(z[4 * q + 2], wv.z, s);
            s = fmaf(z[4 * q + 3], wv.w, s);
        }
        sc[k] = s;
        mx = fmaxf(mx, s);
    }
    float sum = 0.f;
#pragma unroll
    for (int k = 0; k < NEXp; k++) { float e = expf(sc[k] - mx); sc[k] = e; sum += e; }

    // probs + gumbel-max categorical.
    // JAX partitionable threefry (default since 2024): per-element 64-bit
    // counter L -> threefry2x32(key, (hi=0, lo=L)); 32-bit draw = o0 ^ o1.
    float best = -3.4e38f; int bi = 0;
    unsigned Lbase = (unsigned)b * 40u;
#pragma unroll
    for (int k = 0; k < NEXp; k++) {
        float p = sc[k] / sum;
        probs_out[(size_t)b * 40 + k] = p;
        float logit = logf(p);

        unsigned L = Lbase + (unsigned)k;    // < 2^32, so hi word = 0
        unsigned o0, o1;
        threefry2x32_01(0u, L, o0, o1);
        unsigned bits = o0 ^ o1;

        float u = __uint_as_float((bits >> 9) | 0x3f800000u) - 1.0f;
        u = fmaxf(u, 1.17549435e-38f);           // minval = float32 tiny
        float g = -logf(-logf(u));
        float v = logit + g;
        if (v > best) { best = v; bi = k; }      // strict > = first-max tie-break
    }
    g_idx[b] = bi;
}

// ---------- kernel 2: H = relu(Z @ Wc^T + b), 128x128x64 tiles, FFMA2 ----------
__global__ __launch_bounds__(256, 2) void k_gemm(
    const float* __restrict__ triz_bias, float* __restrict__ h_out)
{
    __shared__ __align__(16) float As[HID][128];   // [kk][m]
    __shared__ __align__(16) float Bs[HID][128];   // [kk][n]

    const int m0 = blockIdx.x * 128;
    const int n0 = blockIdx.y * 128;
    const int tid = threadIdx.x;

    // cooperative loads: both tiles K-major, fully coalesced float4s
#pragma unroll
    for (int i = 0; i < 8; i++) {
        int f = tid + i * 256;           // [0, 2048)
        int row = f >> 5;                // kk
        int c4 = f & 31;                 // float4 column
        float4 va = *(const float4*)(g_zt + (size_t)row * BROWS + m0 + c4 * 4);
        *(float4*)(&As[row][c4 * 4]) = va;
        float4 vb = *(const float4*)(g_wt + row * NCOLS + n0 + c4 * 4);
        *(float4*)(&Bs[row][c4 * 4]) = vb;
    }
    __syncthreads();

    const int tx = tid & 15;             // n-dim
    const int ty = tid >> 4;             // m-dim

    unsigned long long acc[8][4];
#pragma unroll
    for (int i = 0; i < 8; i++)
#pragma unroll
        for (int j = 0; j < 4; j++) acc[i][j] = 0ull;

#pragma unroll 8
    for (int kk = 0; kk < HID; kk++) {
        float4 a0 = *(const float4*)(&As[kk][4 * ty]);
        float4 a1 = *(const float4*)(&As[kk][64 + 4 * ty]);
        float4 b0 = *(const float4*)(&Bs[kk][4 * tx]);
        float4 b1 = *(const float4*)(&Bs[kk][64 + 4 * tx]);
        unsigned long long bb0 = pack2(b0.x, b0.y);
        unsigned long long bb1 = pack2(b0.z, b0.w);
        unsigned long long bb2 = pack2(b1.x, b1.y);
        unsigned long long bb3 = pack2(b1.z, b1.w);
        float am[8] = {a0.x, a0.y, a0.z, a0.w, a1.x, a1.y, a1.z, a1.w};
#pragma unroll
        for (int i = 0; i < 8; i++) {
            unsigned long long aa = pack2(am[i], am[i]);
            fma2(acc[i][0], aa, bb0);
            fma2(acc[i][1], aa, bb1);
            fma2(acc[i][2], aa, bb2);
            fma2(acc[i][3], aa, bb3);
        }
    }

    // epilogue: bias + relu + coalesced float4 stores
    float bv[8];
#pragma unroll
    for (int l = 0; l < 4; l++) {
        bv[l]     = triz_bias[n0 + 4 * tx + l];
        bv[4 + l] = triz_bias[n0 + 64 + 4 * tx + l];
    }
#pragma unroll
    for (int i = 0; i < 8; i++) {
        int m = (i < 4) ? (4 * ty + i) : (64 + 4 * ty + (i - 4));
        float* row = h_out + (size_t)(m0 + m) * NCOLS + n0;
        float v[8];
#pragma unroll
        for (int j = 0; j < 4; j++) unpack2(acc[i][j], v[2 * j], v[2 * j + 1]);
        float4 r0, r1;
        r0.x = fmaxf(v[0] + bv[0], 0.f);
        r0.y = fmaxf(v[1] + bv[1], 0.f);
        r0.z = fmaxf(v[2] + bv[2], 0.f);
        r0.w = fmaxf(v[3] + bv[3], 0.f);
        r1.x = fmaxf(v[4] + bv[4], 0.f);
        r1.y = fmaxf(v[5] + bv[5], 0.f);
        r1.z = fmaxf(v[6] + bv[6], 0.f);
        r1.w = fmaxf(v[7] + bv[7], 0.f);
        *(float4*)(row + 4 * tx) = r0;
        *(float4*)(row + 64 + 4 * tx) = r1;
    }
}

// ---------- kernel 3: gather selected expert + decoder ----------
__global__ __launch_bounds__(256) void k_decode(
    const float* __restrict__ dec_w, const float* __restrict__ dec_b,
    const float* __restrict__ h, float* __restrict__ out)
{
    int b = blockIdx.x * 256 + threadIdx.x;
    int idx = g_idx[b];
    const float4* sel = (const float4*)(h + (size_t)b * NCOLS + idx * HID);
    float s[5];
#pragma unroll
    for (int i = 0; i < 5; i++) s[i] = dec_b[i];
#pragma unroll
    for (int q = 0; q < 16; q++) {
        float4 v = sel[q];
#pragma unroll
        for (int i = 0; i < 5; i++) {
            const float* w = dec_w + i * HID + 4 * q;
            s[i] = fmaf(v.x, w[0], s[i]);
            s[i] = fmaf(v.y, w[1], s[i]);
            s[i] = fmaf(v.z, w[2], s[i]);
            s[i] = fmaf(v.w, w[3], s[i]);
        }
    }
#pragma unroll
    for (int i = 0; i < 5; i++) out[(size_t)b * 5 + i] = s[i];
}

// ---------- launch ----------
extern "C" void kernel_launch(void* const* d_in, const int* in_sizes, int n_in,
                              void* d_out, int out_size)
{
    const float* x      = (const float*)d_in[0];
    const float* enc_w  = (const float*)d_in[1];
    const float* enc_b  = (const float*)d_in[2];
    const float* triz_w = (const float*)d_in[3];
    const float* triz_b = (const float*)d_in[4];
    const float* pol_w  = (const float*)d_in[5];
    const float* pol_b  = (const float*)d_in[6];
    const float* dec_w  = (const float*)d_in[7];
    const float* dec_b  = (const float*)d_in[8];

    float* out   = (float*)d_out;
    float* probs = out + (size_t)BROWS * 5;
    float* h     = probs + (size_t)BROWS * 40;

    k_transpose<<<(NCOLS * HID + 255) / 256, 256>>>(triz_w);
    k_encode<<<BROWS / 256, 256>>>(x, enc_w, enc_b, pol_w, pol_b, probs);
    dim3 g2(BROWS / 128, NCOLS / 128);
    k_gemm<<<g2, 256>>>(triz_b, h);
    k_decode<<<BROWS / 256, 256>>>(dec_w, dec_b, h, out);
}

// round 9
// speedup vs baseline: 1.3889x; 1.3889x over previous
#include <cuda_runtime.h>
#include <cuda_bf16.h>
#include <cstdint>

#define BROWS 131072
#define NEXp 40
#define HID 64
#define NCOLS 2560           // 40*64

#define OFF_AH 0
#define OFF_AL 16384
#define OFF_BH 32768
#define OFF_BL 49152
#define GEMM_SMEM 65536

// ---------- device scratch (no allocations allowed) ----------
__device__ __align__(16) unsigned short g_zh[(size_t)BROWS * HID];  // bf16 hi of z, [b][d]
__device__ __align__(16) unsigned short g_zl[(size_t)BROWS * HID];  // bf16 lo of z
__device__ __align__(16) unsigned short g_wh[NCOLS * HID];          // bf16 hi of w, [n][d]
__device__ __align__(16) unsigned short g_wl[NCOLS * HID];          // bf16 lo of w
__device__ int g_idx[BROWS];

// ---------- PTX helpers (all sm_80-era, valid on plain sm_103 target) ----------
__device__ __forceinline__ uint32_t smem_u32(const void* p) {
    uint32_t a;
    asm("{ .reg .u64 t; cvta.to.shared.u64 t, %1; cvt.u32.u64 %0, t; }" : "=r"(a) : "l"(p));
    return a;
}
__device__ __forceinline__ void ldsm_x4(uint32_t* r, uint32_t addr) {
    asm volatile("ldmatrix.sync.aligned.m8n8.x4.shared.b16 {%0,%1,%2,%3}, [%4];"
                 : "=r"(r[0]), "=r"(r[1]), "=r"(r[2]), "=r"(r[3]) : "r"(addr));
}
__device__ __forceinline__ void mma_bf16(float* c, const uint32_t* a, uint32_t b0, uint32_t b1) {
    asm volatile(
        "mma.sync.aligned.m16n8k16.row.col.f32.bf16.bf16.f32 "
        "{%0,%1,%2,%3}, {%4,%5,%6,%7}, {%8,%9}, {%0,%1,%2,%3};"
        : "+f"(c[0]), "+f"(c[1]), "+f"(c[2]), "+f"(c[3])
        : "r"(a[0]), "r"(a[1]), "r"(a[2]), "r"(a[3]), "r"(b0), "r"(b1));
}

// ---------- JAX threefry2x32, key = (0, 1) ----------
__device__ __forceinline__ void threefry2x32_01(unsigned c0, unsigned c1,
                                                unsigned& o0, unsigned& o1) {
    const unsigned k0 = 0u, k1 = 1u, k2 = 0x1BD11BDBu;
    unsigned x0 = c0 + k0;
    unsigned x1 = c1 + k1;
#define TF_R(r) { x0 += x1; x1 = (x1 << (r)) | (x1 >> (32 - (r))); x1 ^= x0; }
    TF_R(13) TF_R(15) TF_R(26) TF_R(6)   x0 += k1; x1 += k2 + 1u;
    TF_R(17) TF_R(29) TF_R(16) TF_R(24)  x0 += k2; x1 += k0 + 2u;
    TF_R(13) TF_R(15) TF_R(26) TF_R(6)   x0 += k0; x1 += k1 + 3u;
    TF_R(17) TF_R(29) TF_R(16) TF_R(24)  x0 += k1; x1 += k2 + 4u;
    TF_R(13) TF_R(15) TF_R(26) TF_R(6)   x0 += k2; x1 += k0 + 5u;
#undef TF_R
    o0 = x0; o1 = x1;
}

// ---------- kernel 0: split expert weights into bf16 hi/lo (no transpose) ----------
__global__ void k_prep(const float* __restrict__ triz_w) {
    int t = blockIdx.x * blockDim.x + threadIdx.x;
    if (t < NCOLS * HID) {
        float v = triz_w[t];
        __nv_bfloat16 h = __float2bfloat16(v);
        __nv_bfloat16 l = __float2bfloat16(v - __bfloat162float(h));
        g_wh[t] = __bfloat16_as_ushort(h);
        g_wl[t] = __bfloat16_as_ushort(l);
    }
}

// ---------- kernel 1: encoder + router softmax + threefry categorical ----------
__global__ __launch_bounds__(256) void k_encode(
    const float* __restrict__ x,
    const float* __restrict__ enc_w, const float* __restrict__ enc_b,
    const float* __restrict__ pol_w, const float* __restrict__ pol_b,
    float* __restrict__ probs_out)
{
    int b = blockIdx.x * 256 + threadIdx.x;

    float xv[5];
#pragma unroll
    for (int j = 0; j < 5; j++) xv[j] = x[b * 5 + j];

    float z[HID];
#pragma unroll
    for (int i = 0; i < HID; i++) {
        float s = enc_b[i];
#pragma unroll
        for (int j = 0; j < 5; j++) s = fmaf(xv[j], enc_w[i * 5 + j], s);
        z[i] = tanhf(s);
    }

    // bf16 hi/lo split of z, packed pairwise, stored [b][64]
    unsigned ph[32], pl[32];
#pragma unroll
    for (int d = 0; d < 32; d++) {
        __nv_bfloat16 h0 = __float2bfloat16(z[2 * d]);
        __nv_bfloat16 h1 = __float2bfloat16(z[2 * d + 1]);
        __nv_bfloat16 l0 = __float2bfloat16(z[2 * d]     - __bfloat162float(h0));
        __nv_bfloat16 l1 = __float2bfloat16(z[2 * d + 1] - __bfloat162float(h1));
        ph[d] = (unsigned)__bfloat16_as_ushort(h0) | ((unsigned)__bfloat16_as_ushort(h1) << 16);
        pl[d] = (unsigned)__bfloat16_as_ushort(l0) | ((unsigned)__bfloat16_as_ushort(l1) << 16);
    }
    uint4* dzh = (uint4*)(g_zh + (size_t)b * HID);
    uint4* dzl = (uint4*)(g_zl + (size_t)b * HID);
#pragma unroll
    for (int q = 0; q < 8; q++) {
        dzh[q] = make_uint4(ph[4 * q], ph[4 * q + 1], ph[4 * q + 2], ph[4 * q + 3]);
        dzl[q] = make_uint4(pl[4 * q], pl[4 * q + 1], pl[4 * q + 2], pl[4 * q + 3]);
    }

    // router scores
    float sc[NEXp];
    float mx = -3.4e38f;
#pragma unroll
    for (int k = 0; k < NEXp; k++) {
        float s = pol_b[k];
        const float4* w = (const float4*)(pol_w + k * HID);
#pragma unroll
        for (int q = 0; q < 16; q++) {
            float4 wv = w[q];
            s = fmaf(z[4 * q + 0], wv.x, s);
            s = fmaf(z[4 * q + 1], wv.y, s);
            s = fmaf(z[4 * q + 2], wv.z, s);
            s = fmaf(z[4 * q + 3], wv.w, s);
        }
        sc[k] = s;
        mx = fmaxf(mx, s);
    }
    float sum = 0.f;
#pragma unroll
    for (int k = 0; k < NEXp; k++) { float e = expf(sc[k] - mx); sc[k] = e; sum += e; }

    // probs + gumbel-max categorical (JAX partitionable threefry: ctr (0, L), bits = o0^o1)
    float best = -3.4e38f; int bi = 0;
    unsigned Lbase = (unsigned)b * 40u;
#pragma unroll
    for (int k = 0; k < NEXp; k++) {
        float p = sc[k] / sum;
        probs_out[(size_t)b * 40 + k] = p;
        float logit = logf(p);

        unsigned L = Lbase + (unsigned)k;
        unsigned o0, o1;
        threefry2x32_01(0u, L, o0, o1);
        unsigned bits = o0 ^ o1;

        float u = __uint_as_float((bits >> 9) | 0x3f800000u) - 1.0f;
        u = fmaxf(u, 1.17549435e-38f);
        float g = -logf(-logf(u));
        float v = logit + g;
        if (v > best) { best = v; bi = k; }
    }
    g_idx[b] = bi;
}

// ---------- kernel 2: mma.sync bf16-split GEMM, CTA tile 128x128, K=64 ----------
// A = z [m][k] bf16 hi/lo, B = w [n][k] bf16 hi/lo (both K-major).
// C = Ah*Bh + Ah*Bl + Al*Bh, fp32 accum. Warp tile 32m x 64n.
__global__ void __launch_bounds__(256, 2) k_gemm_mma(
    const float* __restrict__ bias, float* __restrict__ h_out)
{
    extern __shared__ __align__(1024) char smem[];
    const uint32_t sb = smem_u32(smem);
    const int tid = threadIdx.x, wid = tid >> 5, lane = tid & 31;
    const int m0 = blockIdx.x * 128, n0 = blockIdx.y * 128;
    const int wm = wid & 3;          // m quadrant (32 rows)
    const int wn = wid >> 2;         // n half (64 cols)

    // ---- cooperative smem fill: rows of 128B (64 bf16), SW128 xor swizzle ----
#pragma unroll
    for (int i = 0; i < 4; i++) {
        int f = tid + i * 256;           // 0..1023
        int r = f >> 3;                  // row 0..127
        int c = f & 7;                   // 16B chunk
        int sw = ((c ^ (r & 7)) << 4);
        *(uint4*)(smem + OFF_AH + r * 128 + sw) = ((const uint4*)(g_zh + (size_t)(m0 + r) * HID))[c];
        *(uint4*)(smem + OFF_AL + r * 128 + sw) = ((const uint4*)(g_zl + (size_t)(m0 + r) * HID))[c];
        *(uint4*)(smem + OFF_BH + r * 128 + sw) = ((const uint4*)(g_wh + (size_t)(n0 + r) * HID))[c];
        *(uint4*)(smem + OFF_BL + r * 128 + sw) = ((const uint4*)(g_wl + (size_t)(n0 + r) * HID))[c];
    }
    __syncthreads();

    // ---- ldmatrix address components ----
    // A: lanes 0-15 -> rows m..m+15 (k-lo chunk), lanes 16-31 -> same rows (k-hi chunk)
    const int arow0 = wm * 32 + (lane & 15);            // + mt*16
    const int achunk = (lane >> 4);                     // + kc*2
    // B x4: covers 16 n (two 8-wide tiles) x k16
    const int g = lane >> 3, lr = lane & 7;
    const int brow0 = wn * 64 + ((g & 2) << 2) + lr;    // + ntp*16
    const int bchunk = (g & 1);                         // + kc*2

    float acc[2][8][4];
#pragma unroll
    for (int mt = 0; mt < 2; mt++)
#pragma unroll
        for (int nt = 0; nt < 8; nt++)
#pragma unroll
            for (int q = 0; q < 4; q++) acc[mt][nt][q] = 0.f;

#pragma unroll
    for (int kc = 0; kc < 4; kc++) {
        uint32_t Ah[2][4], Al[2][4];
#pragma unroll
        for (int mt = 0; mt < 2; mt++) {
            int row = arow0 + mt * 16;
            int ch = kc * 2 + achunk;
            uint32_t off = row * 128 + (((ch ^ (row & 7)) & 7) << 4);
            ldsm_x4(Ah[mt], sb + OFF_AH + off);
            ldsm_x4(Al[mt], sb + OFF_AL + off);
        }
#pragma unroll
        for (int ntp = 0; ntp < 4; ntp++) {
            int row = brow0 + ntp * 16;
            int ch = kc * 2 + bchunk;
            uint32_t off = row * 128 + (((ch ^ (row & 7)) & 7) << 4);
            uint32_t Bh[4], Bl[4];
            ldsm_x4(Bh, sb + OFF_BH + off);
            ldsm_x4(Bl, sb + OFF_BL + off);
#pragma unroll
            for (int mt = 0; mt < 2; mt++) {
                mma_bf16(acc[mt][2 * ntp],     Ah[mt], Bh[0], Bh[1]);
                mma_bf16(acc[mt][2 * ntp + 1], Ah[mt], Bh[2], Bh[3]);
                mma_bf16(acc[mt][2 * ntp],     Al[mt], Bh[0], Bh[1]);
                mma_bf16(acc[mt][2 * ntp + 1], Al[mt], Bh[2], Bh[3]);
                mma_bf16(acc[mt][2 * ntp],     Ah[mt], Bl[0], Bl[1]);
                mma_bf16(acc[mt][2 * ntp + 1], Ah[mt], Bl[2], Bl[3]);
            }
        }
    }

    // ---- epilogue: bias + relu, direct float2 stores ----
    // c-frag: c0,c1 -> (row = lane/4, col = (lane%4)*2), c2,c3 -> row+8
    const int erow = m0 + wm * 32 + (lane >> 2);
    const int ecol0 = n0 + wn * 64 + (lane & 3) * 2;
#pragma unroll
    for (int nt = 0; nt < 8; nt++) {
        int col = ecol0 + nt * 8;
        float b0 = bias[col], b1 = bias[col + 1];
#pragma unroll
        for (int mt = 0; mt < 2; mt++) {
            float* p0 = h_out + (size_t)(erow + mt * 16) * NCOLS + col;
            float* p1 = p0 + 8 * NCOLS;
            float2 v0, v1;
            v0.x = fmaxf(acc[mt][nt][0] + b0, 0.f);
            v0.y = fmaxf(acc[mt][nt][1] + b1, 0.f);
            v1.x = fmaxf(acc[mt][nt][2] + b0, 0.f);
            v1.y = fmaxf(acc[mt][nt][3] + b1, 0.f);
            *(float2*)p0 = v0;
            *(float2*)p1 = v1;
        }
    }
}

// ---------- kernel 3: gather selected expert + decoder ----------
__global__ __launch_bounds__(256) void k_decode(
    const float* __restrict__ dec_w, const float* __restrict__ dec_b,
    const float* __restrict__ h, float* __restrict__ out)
{
    int b = blockIdx.x * 256 + threadIdx.x;
    int idx = g_idx[b];
    const float4* sel = (const float4*)(h + (size_t)b * NCOLS + idx * HID);
    float s[5];
#pragma unroll
    for (int i = 0; i < 5; i++) s[i] = dec_b[i];
#pragma unroll
    for (int q = 0; q < 16; q++) {
        float4 v = sel[q];
#pragma unroll
        for (int i = 0; i < 5; i++) {
            const float* w = dec_w + i * HID + 4 * q;
            s[i] = fmaf(v.x, w[0], s[i]);
            s[i] = fmaf(v.y, w[1], s[i]);
            s[i] = fmaf(v.z, w[2], s[i]);
            s[i] = fmaf(v.w, w[3], s[i]);
        }
    }
#pragma unroll
    for (int i = 0; i < 5; i++) out[(size_t)b * 5 + i] = s[i];
}

// ---------- launch ----------
extern "C" void kernel_launch(void* const* d_in, const int* in_sizes, int n_in,
                              void* d_out, int out_size)
{
    const float* x      = (const float*)d_in[0];
    const float* enc_w  = (const float*)d_in[1];
    const float* enc_b  = (const float*)d_in[2];
    const float* triz_w = (const float*)d_in[3];
    const float* triz_b = (const float*)d_in[4];
    const float* pol_w  = (const float*)d_in[5];
    const float* pol_b  = (const float*)d_in[6];
    const float* dec_w  = (const float*)d_in[7];
    const float* dec_b  = (const float*)d_in[8];

    float* out   = (float*)d_out;
    float* probs = out + (size_t)BROWS * 5;
    float* h     = probs + (size_t)BROWS * 40;

    cudaFuncSetAttribute(k_gemm_mma, cudaFuncAttributeMaxDynamicSharedMemorySize, GEMM_SMEM);

    k_prep<<<(NCOLS * HID + 255) / 256, 256>>>(triz_w);
    k_encode<<<BROWS / 256, 256>>>(x, enc_w, enc_b, pol_w, pol_b, probs);
    dim3 g2(BROWS / 128, NCOLS / 128);
    k_gemm_mma<<<g2, 256, GEMM_SMEM>>>(triz_b, h);
    k_decode<<<BROWS / 256, 256>>>(dec_w, dec_b, h, out);
}